// round 7
// baseline (speedup 1.0000x reference)
#include <cuda_runtime.h>

// ADDLoss, single fused kernel with internal setup->main spin barrier.
//  blocks [0,64):    per-batch coeffs S=M^T M, c=2M^T t, t2 -> g_coef;
//                    pack points AoS -> SoA u64 pairs; trans-norm term -> g_sum;
//                    arrive on g_setup_done, last sets g_ready.
//  blocks [64,2112): spin on g_ready, then warp-per-batch-element f32x2
//                    quadratic-form loop; deterministic fixed-point reduce.
// Last main ticket resets flags for graph replay.

#define BATCH      16384
#define NPTS       500
#define NPAIRS     250
#define NQUADS     125
#define NOBJ       30
#define OBJ_STRIDE 256
#define WARPS_PB   8
#define THREADS_PB (WARPS_PB * 32)        // 256
#define NBLOCKS    (BATCH / WARPS_PB)     // 2048
#define SETUP_BLOCKS 64
#define TOTAL_BLOCKS (SETUP_BLOCKS + NBLOCKS)

#define FP_SCALE     68719476736.0        // 2^36
#define INV_FP_SCALE (1.0 / 68719476736.0)

typedef unsigned long long u64;

__device__ u64    g_px[NOBJ * OBJ_STRIDE];
__device__ u64    g_py[NOBJ * OBJ_STRIDE];
__device__ u64    g_pz[NOBJ * OBJ_STRIDE];
__device__ float4 g_coef[BATCH * 3];
__device__ u64    g_sum;
__device__ unsigned int g_count;
__device__ unsigned int g_setup_done;
__device__ unsigned int g_ready;

__device__ __forceinline__ u64 pack2(float lo, float hi) {
    u64 d; asm("mov.b64 %0, {%1, %2};" : "=l"(d) : "f"(lo), "f"(hi)); return d;
}
__device__ __forceinline__ void unpack2(float& lo, float& hi, u64 v) {
    asm("mov.b64 {%0, %1}, %2;" : "=f"(lo), "=f"(hi) : "l"(v));
}
__device__ __forceinline__ u64 mul2(u64 a, u64 b) {
    u64 d; asm("mul.rn.f32x2 %0, %1, %2;" : "=l"(d) : "l"(a), "l"(b)); return d;
}
__device__ __forceinline__ u64 add2(u64 a, u64 b) {
    u64 d; asm("add.rn.f32x2 %0, %1, %2;" : "=l"(d) : "l"(a), "l"(b)); return d;
}
__device__ __forceinline__ u64 fma2(u64 a, u64 b, u64 c) {
    u64 d; asm("fma.rn.f32x2 %0, %1, %2, %3;" : "=l"(d) : "l"(a), "l"(b), "l"(c)); return d;
}
__device__ __forceinline__ float sqrt_abs(float x) {
    float r; asm("sqrt.approx.f32 %0, %1;" : "=f"(r) : "f"(fabsf(x))); return r;
}
__device__ __forceinline__ unsigned int ld_cg_u32(const unsigned int* p) {
    unsigned int v; asm volatile("ld.global.cg.u32 %0, [%1];" : "=r"(v) : "l"(p)); return v;
}

__global__ __launch_bounds__(THREADS_PB)
void addloss_all(const float* __restrict__ points,
                 const float* __restrict__ pred_r,
                 const float* __restrict__ pred_t,
                 const float* __restrict__ gt_r,
                 const float* __restrict__ gt_t,
                 const int*   __restrict__ obj_ids,
                 float*       __restrict__ out)
{
    // =================== SETUP PATH: blocks [0, 64) =========================
    if (blockIdx.x < SETUP_BLOCKS) {
        const int tid = blockIdx.x * 256 + threadIdx.x;   // 0..16383

        // --- points pack: pairs 0..7499 spread over first 7500 tids ---
        if (tid < NOBJ * NPAIRS) {
            const int o = tid / NPAIRS;
            const int j = tid - o * NPAIRS;
            const float* p = points + (size_t)o * (NPTS * 3) + 6 * j;
            g_px[o * OBJ_STRIDE + j] = pack2(p[0], p[3]);
            g_py[o * OBJ_STRIDE + j] = pack2(p[1], p[4]);
            g_pz[o * OBJ_STRIDE + j] = pack2(p[2], p[5]);
        }

        // --- coefficients for batch element `tid` ---
        const int b = tid;
        const float4 qp = reinterpret_cast<const float4*>(pred_r)[b];
        const float4 qg = reinterpret_cast<const float4*>(gt_r)[b];
        float pw = qp.x, px_ = qp.y, py_ = qp.z, pz_ = qp.w;
        float gw = qg.x, gx_ = qg.y, gy_ = qg.z, gz_ = qg.w;

        const float m00 = -2.f*(py_*py_ + pz_*pz_ - gy_*gy_ - gz_*gz_);
        const float m01 =  2.f*(px_*py_ - pw*pz_ - gx_*gy_ + gw*gz_);
        const float m02 =  2.f*(px_*pz_ + pw*py_ - gx_*gz_ - gw*gy_);
        const float m10 =  2.f*(px_*py_ + pw*pz_ - gx_*gy_ - gw*gz_);
        const float m11 = -2.f*(px_*px_ + pz_*pz_ - gx_*gx_ - gz_*gz_);
        const float m12 =  2.f*(py_*pz_ - pw*px_ - gy_*gz_ + gw*gx_);
        const float m20 =  2.f*(px_*pz_ - pw*py_ - gx_*gz_ + gw*gy_);
        const float m21 =  2.f*(py_*pz_ + pw*px_ - gy_*gz_ - gw*gx_);
        const float m22 = -2.f*(px_*px_ + py_*py_ - gx_*gx_ - gy_*gy_);

        const float tx = pred_t[3*b+0] - gt_t[3*b+0];
        const float ty = pred_t[3*b+1] - gt_t[3*b+1];
        const float tz = pred_t[3*b+2] - gt_t[3*b+2];
        const float t2 = tx*tx + ty*ty + tz*tz;

        float4 c0, c1, c2;
        c0.x = m00*m00 + m10*m10 + m20*m20;
        c0.y = m01*m01 + m11*m11 + m21*m21;
        c0.z = m02*m02 + m12*m12 + m22*m22;
        c0.w = 2.f*(m00*m01 + m10*m11 + m20*m21);
        c1.x = 2.f*(m00*m02 + m10*m12 + m20*m22);
        c1.y = 2.f*(m01*m02 + m11*m12 + m21*m22);
        c1.z = 2.f*(m00*tx + m10*ty + m20*tz);
        c1.w = 2.f*(m01*tx + m11*ty + m21*tz);
        c2.x = 2.f*(m02*tx + m12*ty + m22*tz);
        c2.y = t2; c2.z = 0.f; c2.w = 0.f;
        g_coef[3*b + 0] = c0;
        g_coef[3*b + 1] = c1;
        g_coef[3*b + 2] = c2;

        // trans-norm term, block tree-reduce (fixed order) -> int atomic
        __shared__ float sh[256];
        sh[threadIdx.x] = sqrt_abs(t2);
        __syncthreads();
        #pragma unroll
        for (int st = 128; st > 0; st >>= 1) {
            if (threadIdx.x < st) sh[threadIdx.x] += sh[threadIdx.x + st];
            __syncthreads();
        }
        if (threadIdx.x == 0) {
            const u64 q = (u64)__double2ll_rn((double)sh[0] * FP_SCALE);
            atomicAdd(&g_sum, q);
            __threadfence();                       // publish coeffs + pack + sum
            const unsigned int done = atomicAdd(&g_setup_done, 1u);
            if (done == SETUP_BLOCKS - 1)
                atomicExch(&g_ready, 1u);          // release main blocks
        }
        return;
    }

    // =================== MAIN PATH: blocks [64, 2112) =======================
    const int mblk        = blockIdx.x - SETUP_BLOCKS;
    const int warp_in_blk = threadIdx.x >> 5;
    const int lane        = threadIdx.x & 31;
    const int b           = mblk * WARPS_PB + warp_in_blk;

    __shared__ float sh_val[WARPS_PB];

    // spin until setup published (wave-1 setup blocks are co-resident: bid order)
    if (threadIdx.x == 0) {
        while (ld_cg_u32(&g_ready) == 0u) __nanosleep(64);
    }
    __syncthreads();
    __threadfence();   // acquire: order coeff/point reads after flag

    const float4 k0 = g_coef[3*b + 0];
    const float4 k1 = g_coef[3*b + 1];
    const float4 k2 = g_coef[3*b + 2];

    const u64 S00 = pack2(k0.x, k0.x), S11 = pack2(k0.y, k0.y), S22 = pack2(k0.z, k0.z);
    const u64 S01 = pack2(k0.w, k0.w), S02 = pack2(k1.x, k1.x), S12 = pack2(k1.y, k1.y);
    const u64 C0  = pack2(k1.z, k1.z), C1  = pack2(k1.w, k1.w), C2  = pack2(k2.x, k2.x);
    const u64 T2  = pack2(k2.y, k2.y);

    int oid = obj_ids[b];
    oid = min(max(oid, 0), NOBJ - 1);
    const ulonglong2* __restrict__ BX =
        reinterpret_cast<const ulonglong2*>(g_px) + oid * (OBJ_STRIDE / 2);
    const ulonglong2* __restrict__ BY =
        reinterpret_cast<const ulonglong2*>(g_py) + oid * (OBJ_STRIDE / 2);
    const ulonglong2* __restrict__ BZ =
        reinterpret_cast<const ulonglong2*>(g_pz) + oid * (OBJ_STRIDE / 2);

    float acc0 = 0.f, acc1 = 0.f;

    #define PAIR_TERM(PX, PY, PZ, ACC) do {                                    \
        u64 U  = fma2(S02, (PZ), fma2(S01, (PY), mul2(S00, (PX))));            \
        u64 V  = fma2(S12, (PZ), mul2(S11, (PY)));                             \
        u64 W  = mul2(S22, (PZ));                                              \
        u64 A2 = fma2((PZ), W, fma2((PY), V, mul2((PX), U)));                  \
        u64 LIN = fma2(C0, (PX), fma2(C1, (PY), fma2(C2, (PZ), T2)));          \
        u64 B2 = add2(A2, LIN);                                                \
        float a2l, a2h, b2l, b2h;                                              \
        unpack2(a2l, a2h, A2);                                                 \
        unpack2(b2l, b2h, B2);                                                 \
        ACC += (sqrt_abs(a2l) + sqrt_abs(b2l))                                 \
             + (sqrt_abs(a2h) + sqrt_abs(b2h));                                \
    } while (0)

    const ulonglong2 x0 = BX[lane],      y0 = BY[lane],      z0 = BZ[lane];
    const ulonglong2 x1 = BX[lane + 32], y1 = BY[lane + 32], z1 = BZ[lane + 32];

    PAIR_TERM(x0.x, y0.x, z0.x, acc0);
    PAIR_TERM(x0.y, y0.y, z0.y, acc1);

    const ulonglong2 x2 = BX[lane + 64], y2 = BY[lane + 64], z2 = BZ[lane + 64];
    PAIR_TERM(x1.x, y1.x, z1.x, acc0);
    PAIR_TERM(x1.y, y1.y, z1.y, acc1);

    if (lane < NQUADS - 96) {   // lane < 29
        const ulonglong2 x3 = BX[lane + 96], y3 = BY[lane + 96], z3 = BZ[lane + 96];
        PAIR_TERM(x2.x, y2.x, z2.x, acc0);
        PAIR_TERM(x2.y, y2.y, z2.y, acc1);
        PAIR_TERM(x3.x, y3.x, z3.x, acc0);
        PAIR_TERM(x3.y, y3.y, z3.y, acc1);
    } else {
        PAIR_TERM(x2.x, y2.x, z2.x, acc0);
        PAIR_TERM(x2.y, y2.y, z2.y, acc1);
    }
    #undef PAIR_TERM

    float s = acc0 + acc1;

    #pragma unroll
    for (int off = 16; off > 0; off >>= 1)
        s += __shfl_down_sync(0xffffffffu, s, off);

    if (lane == 0)
        sh_val[warp_in_blk] = s * (1.0f / NPTS);
    __syncthreads();

    if (threadIdx.x == 0) {
        float blk = 0.f;
        #pragma unroll
        for (int w = 0; w < WARPS_PB; w++) blk += sh_val[w];

        const u64 q = (u64)__double2ll_rn((double)blk * FP_SCALE);
        atomicAdd(&g_sum, q);
        __threadfence();
        const unsigned int ticket = atomicAdd(&g_count, 1u);
        if (ticket == NBLOCKS - 1) {
            // all main blocks passed the spin; safe to reset for graph replay
            const u64 total = atomicExch(&g_sum, 0ULL);
            g_count = 0u;
            g_setup_done = 0u;
            g_ready = 0u;
            out[0] = (float)((double)total * INV_FP_SCALE * (1.0 / BATCH));
        }
    }
}

extern "C" void kernel_launch(void* const* d_in, const int* in_sizes, int n_in,
                              void* d_out, int out_size)
{
    const float* pred_r  = (const float*)d_in[0];
    const float* pred_t  = (const float*)d_in[1];
    const float* gt_r    = (const float*)d_in[2];
    const float* gt_t    = (const float*)d_in[3];
    const int*   obj_ids = (const int*)  d_in[4];
    const float* points  = (const float*)d_in[5];
    float* out = (float*)d_out;

    addloss_all<<<TOTAL_BLOCKS, THREADS_PB>>>(points, pred_r, pred_t, gt_r, gt_t,
                                              obj_ids, out);
}

// round 8
// speedup vs baseline: 1.0933x; 1.0933x over previous
#include <cuda_runtime.h>

// ADDLoss, two launches, all-scalar math (R2-R7 lesson: f32x2 does not reduce
// fma-pipe work on sm_103a; its packing overhead + prep launch cost more than
// it saved).
//  launch 1 (64 blocks): per-batch coeffs S=M^T M (off-diag doubled), c=2M^T t,
//                        t2 -> g_coef; trans-norm term reduced into g_sum.
//  launch 2 (2048 blocks, warp per batch elem): broadcast coeff load, scalar
//                        FFMA quadratic-form over 500 AoS points (float4 LDG.128),
//                        MUFU sqrt with folded |x|, deterministic fixed-point
//                        integer reduce; last block writes out.

#define BATCH      16384
#define NPTS       500
#define NQUADS     125
#define NOBJ       30
#define WARPS_PB   8
#define THREADS_PB (WARPS_PB * 32)      // 256
#define NBLOCKS    (BATCH / WARPS_PB)   // 2048
#define SETUP_BLOCKS (BATCH / 256)      // 64

#define FP_SCALE     68719476736.0      // 2^36
#define INV_FP_SCALE (1.0 / 68719476736.0)

typedef unsigned long long u64;

__device__ float4 g_coef[BATCH * 3];    // {s00,s11,s22,s01d} {s02d,s12d,c0,c1} {c2,t2,-,-}
__device__ u64    g_sum;
__device__ unsigned int g_count;

__device__ __forceinline__ float sqrt_abs(float x) {
    // a2/b2 >= 0 up to rounding; fabs folds into the MUFU input modifier.
    float r; asm("sqrt.approx.f32 %0, %1;" : "=f"(r) : "f"(fabsf(x))); return r;
}

// ---- launch 1: coefficients + trans term -----------------------------------
__global__ __launch_bounds__(256)
void addloss_setup(const float* __restrict__ pred_r,
                   const float* __restrict__ pred_t,
                   const float* __restrict__ gt_r,
                   const float* __restrict__ gt_t)
{
    const int b = blockIdx.x * 256 + threadIdx.x;

    const float4 qp = reinterpret_cast<const float4*>(pred_r)[b];
    const float4 qg = reinterpret_cast<const float4*>(gt_r)[b];
    float pw = qp.x, px_ = qp.y, py_ = qp.z, pz_ = qp.w;
    float gw = qg.x, gx_ = qg.y, gy_ = qg.z, gz_ = qg.w;

    const float m00 = -2.f*(py_*py_ + pz_*pz_ - gy_*gy_ - gz_*gz_);
    const float m01 =  2.f*(px_*py_ - pw*pz_ - gx_*gy_ + gw*gz_);
    const float m02 =  2.f*(px_*pz_ + pw*py_ - gx_*gz_ - gw*gy_);
    const float m10 =  2.f*(px_*py_ + pw*pz_ - gx_*gy_ - gw*gz_);
    const float m11 = -2.f*(px_*px_ + pz_*pz_ - gx_*gx_ - gz_*gz_);
    const float m12 =  2.f*(py_*pz_ - pw*px_ - gy_*gz_ + gw*gx_);
    const float m20 =  2.f*(px_*pz_ - pw*py_ - gx_*gz_ + gw*gy_);
    const float m21 =  2.f*(py_*pz_ + pw*px_ - gy_*gz_ - gw*gx_);
    const float m22 = -2.f*(px_*px_ + py_*py_ - gx_*gx_ - gy_*gy_);

    const float tx = pred_t[3*b+0] - gt_t[3*b+0];
    const float ty = pred_t[3*b+1] - gt_t[3*b+1];
    const float tz = pred_t[3*b+2] - gt_t[3*b+2];
    const float t2 = tx*tx + ty*ty + tz*tz;

    float4 c0, c1, c2;
    c0.x = m00*m00 + m10*m10 + m20*m20;            // s00
    c0.y = m01*m01 + m11*m11 + m21*m21;            // s11
    c0.z = m02*m02 + m12*m12 + m22*m22;            // s22
    c0.w = 2.f*(m00*m01 + m10*m11 + m20*m21);      // s01d
    c1.x = 2.f*(m00*m02 + m10*m12 + m20*m22);      // s02d
    c1.y = 2.f*(m01*m02 + m11*m12 + m21*m22);      // s12d
    c1.z = 2.f*(m00*tx + m10*ty + m20*tz);         // c0
    c1.w = 2.f*(m01*tx + m11*ty + m21*tz);         // c1
    c2.x = 2.f*(m02*tx + m12*ty + m22*tz);         // c2
    c2.y = t2; c2.z = 0.f; c2.w = 0.f;
    g_coef[3*b + 0] = c0;
    g_coef[3*b + 1] = c1;
    g_coef[3*b + 2] = c2;

    // trans-norm contribution: fixed-order block reduce -> int atomic
    __shared__ float sh[256];
    sh[threadIdx.x] = sqrt_abs(t2);
    __syncthreads();
    #pragma unroll
    for (int st = 128; st > 0; st >>= 1) {
        if (threadIdx.x < st) sh[threadIdx.x] += sh[threadIdx.x + st];
        __syncthreads();
    }
    if (threadIdx.x == 0) {
        const u64 q = (u64)__double2ll_rn((double)sh[0] * FP_SCALE);
        atomicAdd(&g_sum, q);
    }
}

// ---- launch 2: hot kernel ---------------------------------------------------
__global__ __launch_bounds__(THREADS_PB)
void addloss_main(const int*   __restrict__ obj_ids,
                  const float* __restrict__ points,
                  float*       __restrict__ out)
{
    const int warp_in_blk = threadIdx.x >> 5;
    const int lane        = threadIdx.x & 31;
    const int b           = blockIdx.x * WARPS_PB + warp_in_blk;

    __shared__ float sh_val[WARPS_PB];

    // broadcast coefficient loads (uniform address per warp)
    const float4 k0 = g_coef[3*b + 0];
    const float4 k1 = g_coef[3*b + 1];
    const float4 k2 = g_coef[3*b + 2];
    const float s00 = k0.x, s11 = k0.y, s22 = k0.z, s01 = k0.w;
    const float s02 = k1.x, s12 = k1.y, c0  = k1.z, c1  = k1.w;
    const float c2  = k2.x, t2  = k2.y;

    int oid = obj_ids[b];
    oid = min(max(oid, 0), NOBJ - 1);
    // object offset = oid*1500 floats = 6000 B (16B aligned) -> float4 legal
    const float4* __restrict__ pb4 =
        reinterpret_cast<const float4*>(points + (size_t)oid * (NPTS * 3));

    float acc0 = 0.f, acc1 = 0.f;

    // 13 FFMA-class + 2 MUFU(|x| folded) + 2 FADD per point
    #define POINT_TERM(PX, PY, PZ, ACC) do {                                   \
        const float _px = (PX), _py = (PY), _pz = (PZ);                        \
        const float _U  = fmaf(s02, _pz, fmaf(s01, _py, s00*_px));             \
        const float _V  = fmaf(s12, _pz, s11*_py);                             \
        const float _W  = s22*_pz;                                             \
        const float _a2 = fmaf(_pz, _W, fmaf(_py, _V, _px*_U));                \
        const float _ln = fmaf(c0, _px, fmaf(c1, _py, fmaf(c2, _pz, t2)));     \
        const float _b2 = _a2 + _ln;                                           \
        ACC += sqrt_abs(_a2) + sqrt_abs(_b2);                                  \
    } while (0)

    #define QUAD(V0, V1, V2) do {                                              \
        POINT_TERM((V0).x, (V0).y, (V0).z, acc0);                              \
        POINT_TERM((V0).w, (V1).x, (V1).y, acc1);                              \
        POINT_TERM((V1).z, (V1).w, (V2).x, acc0);                              \
        POINT_TERM((V2).y, (V2).z, (V2).w, acc1);                              \
    } while (0)

    // 125 quads lane-strided; front-batch 2 quads of loads, stream the rest.
    const float4 a0 = pb4[3*lane + 0],  a1 = pb4[3*lane + 1],  a2v = pb4[3*lane + 2];
    const float4 b0 = pb4[3*(lane+32)], b1 = pb4[3*(lane+32)+1], b2v = pb4[3*(lane+32)+2];

    QUAD(a0, a1, a2v);

    const float4 d0 = pb4[3*(lane+64)], d1 = pb4[3*(lane+64)+1], d2v = pb4[3*(lane+64)+2];
    QUAD(b0, b1, b2v);

    if (lane < NQUADS - 96) {   // lane < 29
        const float4 e0 = pb4[3*(lane+96)], e1 = pb4[3*(lane+96)+1], e2v = pb4[3*(lane+96)+2];
        QUAD(d0, d1, d2v);
        QUAD(e0, e1, e2v);
    } else {
        QUAD(d0, d1, d2v);
    }
    #undef QUAD
    #undef POINT_TERM

    float s = acc0 + acc1;

    #pragma unroll
    for (int off = 16; off > 0; off >>= 1)
        s += __shfl_down_sync(0xffffffffu, s, off);

    if (lane == 0)
        sh_val[warp_in_blk] = s * (1.0f / NPTS);
    __syncthreads();

    if (threadIdx.x == 0) {
        float blk = 0.f;
        #pragma unroll
        for (int w = 0; w < WARPS_PB; w++) blk += sh_val[w];

        const u64 q = (u64)__double2ll_rn((double)blk * FP_SCALE);
        atomicAdd(&g_sum, q);
        __threadfence();
        const unsigned int ticket = atomicAdd(&g_count, 1u);
        if (ticket == NBLOCKS - 1) {
            const u64 total = atomicExch(&g_sum, 0ULL);  // read + reset for replay
            g_count = 0u;
            out[0] = (float)((double)total * INV_FP_SCALE * (1.0 / BATCH));
        }
    }
}

extern "C" void kernel_launch(void* const* d_in, const int* in_sizes, int n_in,
                              void* d_out, int out_size)
{
    const float* pred_r  = (const float*)d_in[0];
    const float* pred_t  = (const float*)d_in[1];
    const float* gt_r    = (const float*)d_in[2];
    const float* gt_t    = (const float*)d_in[3];
    const int*   obj_ids = (const int*)  d_in[4];
    const float* points  = (const float*)d_in[5];
    float* out = (float*)d_out;

    addloss_setup<<<SETUP_BLOCKS, 256>>>(pred_r, pred_t, gt_r, gt_t);
    addloss_main<<<NBLOCKS, THREADS_PB>>>(obj_ids, points, out);
}

// round 9
// speedup vs baseline: 1.0970x; 1.0033x over previous
#include <cuda_runtime.h>

// ADDLoss — single launch, all scalar.
//   out = mean_b( mean_n||Mp_n + t|| + mean_n||Mp_n|| + ||t|| ), M = Rp-Rg, t = tp-tg
// Warp per batch element. Prologue (redundant across lanes, amortized over 500
// points): quats -> M -> S = M^T M (off-diag doubled), c = 2 M^T t, t2.
// Loop: a2 = p^T S p (Horner, 9 FFMA-class), b2 = a2 + c.p + t2 (4+1),
// norms via sqrt.approx with |x| folded. Deterministic fixed-point int reduce.
// Lessons baked in: f32x2 gains nothing on sm_103a (R2-R8); every extra launch
// costs 1.7-3 us while the inline prologue costs ~1 us (R4/R6/R8).

#define BATCH      16384
#define NPTS       500
#define NQUADS     125
#define NOBJ       30
#define WARPS_PB   8
#define THREADS_PB (WARPS_PB * 32)      // 256
#define NBLOCKS    (BATCH / WARPS_PB)   // 2048

#define FP_SCALE     68719476736.0      // 2^36
#define INV_FP_SCALE (1.0 / 68719476736.0)

typedef unsigned long long u64;

__device__ u64 g_sum;                   // zero-init; self-resets each launch
__device__ unsigned int g_count;

__device__ __forceinline__ float sqrt_abs(float x) {
    // a2/b2 >= 0 up to rounding; |x| guards tiny-negative cancellation.
    float r; asm("sqrt.approx.f32 %0, %1;" : "=f"(r) : "f"(fabsf(x))); return r;
}

__global__ __launch_bounds__(THREADS_PB)
void addloss_kernel(const float* __restrict__ pred_r,
                    const float* __restrict__ pred_t,
                    const float* __restrict__ gt_r,
                    const float* __restrict__ gt_t,
                    const int*   __restrict__ obj_ids,
                    const float* __restrict__ points,
                    float*       __restrict__ out)
{
    const int warp_in_blk = threadIdx.x >> 5;
    const int lane        = threadIdx.x & 31;
    const int b           = blockIdx.x * WARPS_PB + warp_in_blk;

    __shared__ float sh_val[WARPS_PB];

    // ---- independent loads first (hoistable above the serial quat chain) ----
    int oid = obj_ids[b];
    oid = min(max(oid, 0), NOBJ - 1);
    // object offset = oid*1500 floats = 6000 B (16B aligned) -> float4 legal
    const float4* __restrict__ pb4 =
        reinterpret_cast<const float4*>(points + (size_t)oid * (NPTS * 3));

    const float4 a0 = pb4[3*lane + 0],   a1 = pb4[3*lane + 1],   a2v = pb4[3*lane + 2];
    const float4 b0 = pb4[3*(lane+32)],  b1 = pb4[3*(lane+32)+1], b2v = pb4[3*(lane+32)+2];

    // ---- per-warp prologue (redundant across lanes; ~70 FMA, amortized) ----
    const float4 qp = reinterpret_cast<const float4*>(pred_r)[b];
    const float4 qg = reinterpret_cast<const float4*>(gt_r)[b];
    const float pw = qp.x, px_ = qp.y, py_ = qp.z, pz_ = qp.w;
    const float gw = qg.x, gx_ = qg.y, gy_ = qg.z, gz_ = qg.w;

    const float m00 = -2.f*(py_*py_ + pz_*pz_ - gy_*gy_ - gz_*gz_);
    const float m01 =  2.f*(px_*py_ - pw*pz_ - gx_*gy_ + gw*gz_);
    const float m02 =  2.f*(px_*pz_ + pw*py_ - gx_*gz_ - gw*gy_);
    const float m10 =  2.f*(px_*py_ + pw*pz_ - gx_*gy_ - gw*gz_);
    const float m11 = -2.f*(px_*px_ + pz_*pz_ - gx_*gx_ - gz_*gz_);
    const float m12 =  2.f*(py_*pz_ - pw*px_ - gy_*gz_ + gw*gx_);
    const float m20 =  2.f*(px_*pz_ - pw*py_ - gx_*gz_ + gw*gy_);
    const float m21 =  2.f*(py_*pz_ + pw*px_ - gy_*gz_ - gw*gx_);
    const float m22 = -2.f*(px_*px_ + py_*py_ - gx_*gx_ - gy_*gy_);

    const float tx = pred_t[3*b+0] - gt_t[3*b+0];
    const float ty = pred_t[3*b+1] - gt_t[3*b+1];
    const float tz = pred_t[3*b+2] - gt_t[3*b+2];
    const float t2 = tx*tx + ty*ty + tz*tz;

    const float s00 = m00*m00 + m10*m10 + m20*m20;
    const float s11 = m01*m01 + m11*m11 + m21*m21;
    const float s22 = m02*m02 + m12*m12 + m22*m22;
    const float s01 = 2.f*(m00*m01 + m10*m11 + m20*m21);
    const float s02 = 2.f*(m00*m02 + m10*m12 + m20*m22);
    const float s12 = 2.f*(m01*m02 + m11*m12 + m21*m22);
    const float c0  = 2.f*(m00*tx + m10*ty + m20*tz);
    const float c1  = 2.f*(m01*tx + m11*ty + m21*tz);
    const float c2  = 2.f*(m02*tx + m12*ty + m22*tz);

    float acc0 = 0.f, acc1 = 0.f;

    // 13 FFMA-class + 2 MUFU + 2 FADD per point
    #define POINT_TERM(PX, PY, PZ, ACC) do {                                   \
        const float _px = (PX), _py = (PY), _pz = (PZ);                        \
        const float _U  = fmaf(s02, _pz, fmaf(s01, _py, s00*_px));             \
        const float _V  = fmaf(s12, _pz, s11*_py);                             \
        const float _W  = s22*_pz;                                             \
        const float _a2 = fmaf(_pz, _W, fmaf(_py, _V, _px*_U));                \
        const float _ln = fmaf(c0, _px, fmaf(c1, _py, fmaf(c2, _pz, t2)));     \
        const float _b2 = _a2 + _ln;                                           \
        ACC += sqrt_abs(_a2) + sqrt_abs(_b2);                                  \
    } while (0)

    #define QUAD(V0, V1, V2) do {                                              \
        POINT_TERM((V0).x, (V0).y, (V0).z, acc0);                              \
        POINT_TERM((V0).w, (V1).x, (V1).y, acc1);                              \
        POINT_TERM((V1).z, (V1).w, (V2).x, acc0);                              \
        POINT_TERM((V2).y, (V2).z, (V2).w, acc1);                              \
    } while (0)

    QUAD(a0, a1, a2v);

    const float4 d0 = pb4[3*(lane+64)], d1 = pb4[3*(lane+64)+1], d2v = pb4[3*(lane+64)+2];
    QUAD(b0, b1, b2v);

    if (lane < NQUADS - 96) {   // lane < 29: 4th strided quad
        const float4 e0 = pb4[3*(lane+96)], e1 = pb4[3*(lane+96)+1], e2v = pb4[3*(lane+96)+2];
        QUAD(d0, d1, d2v);
        QUAD(e0, e1, e2v);
    } else {
        QUAD(d0, d1, d2v);
    }
    #undef QUAD
    #undef POINT_TERM

    float s = acc0 + acc1;

    // warp reduce (fixed order -> deterministic)
    #pragma unroll
    for (int off = 16; off > 0; off >>= 1)
        s += __shfl_down_sync(0xffffffffu, s, off);

    if (lane == 0)
        sh_val[warp_in_blk] = fmaf(s, 1.0f / NPTS, sqrt_abs(t2));  // + trans term
    __syncthreads();

    if (threadIdx.x == 0) {
        float blk = 0.f;
        #pragma unroll
        for (int w = 0; w < WARPS_PB; w++) blk += sh_val[w];

        // deterministic grid reduction: fixed-point integer atomic
        const u64 q = (u64)__double2ll_rn((double)blk * FP_SCALE);
        atomicAdd(&g_sum, q);
        __threadfence();
        const unsigned int ticket = atomicAdd(&g_count, 1u);
        if (ticket == NBLOCKS - 1) {
            const u64 total = atomicExch(&g_sum, 0ULL);  // read + reset for replay
            g_count = 0u;
            out[0] = (float)((double)total * INV_FP_SCALE * (1.0 / BATCH));
        }
    }
}

extern "C" void kernel_launch(void* const* d_in, const int* in_sizes, int n_in,
                              void* d_out, int out_size)
{
    const float* pred_r  = (const float*)d_in[0];
    const float* pred_t  = (const float*)d_in[1];
    const float* gt_r    = (const float*)d_in[2];
    const float* gt_t    = (const float*)d_in[3];
    const int*   obj_ids = (const int*)  d_in[4];
    const float* points  = (const float*)d_in[5];
    float* out = (float*)d_out;

    addloss_kernel<<<NBLOCKS, THREADS_PB>>>(pred_r, pred_t, gt_r, gt_t,
                                            obj_ids, points, out);
}

// round 10
// speedup vs baseline: 1.1100x; 1.0118x over previous
#include <cuda_runtime.h>

// ADDLoss — single launch, scalar math, BLOCK-SHARED prologue.
// Block = 8 batch elements. Warp 0 computes all 8 coefficient sets in parallel
// (lane l < 8 runs the serial quat->S/c chain for element l): the ~100-instr
// prologue issues ONCE per block instead of once per warp (R9 lesson: the
// redundant prologue was ~27% of all issue slots). Main warps front-batch
// their point loads BEFORE the barrier so the prologue hides under load latency.
// Loop per point: a2 = p^T S p (9 FFMA), b2 = a2 + c.p + t2 (4), 2 MUFU sqrt.
// Grid reduce: deterministic fixed-point integer atomics.

#define BATCH      16384
#define NPTS       500
#define NQUADS     125
#define NOBJ       30
#define WARPS_PB   8
#define THREADS_PB (WARPS_PB * 32)      // 256
#define NBLOCKS    (BATCH / WARPS_PB)   // 2048

#define FP_SCALE     68719476736.0      // 2^36
#define INV_FP_SCALE (1.0 / 68719476736.0)

typedef unsigned long long u64;

__device__ u64 g_sum;                   // zero-init; self-resets each launch
__device__ unsigned int g_count;

__device__ __forceinline__ float sqrt_abs(float x) {
    float r; asm("sqrt.approx.f32 %0, %1;" : "=f"(r) : "f"(fabsf(x))); return r;
}

__global__ __launch_bounds__(THREADS_PB)
void addloss_kernel(const float* __restrict__ pred_r,
                    const float* __restrict__ pred_t,
                    const float* __restrict__ gt_r,
                    const float* __restrict__ gt_t,
                    const int*   __restrict__ obj_ids,
                    const float* __restrict__ points,
                    float*       __restrict__ out)
{
    const int warp_in_blk = threadIdx.x >> 5;
    const int lane        = threadIdx.x & 31;
    const int b           = blockIdx.x * WARPS_PB + warp_in_blk;

    // sh_coef[w][12]: {s00,s11,s22,s01d, s02d,s12d,c0,c1, c2,t2,pad,pad}
    __shared__ float sh_coef[WARPS_PB][12];
    __shared__ float sh_val[WARPS_PB];

    // ---- every warp: issue its point loads first (independent of prologue) ----
    int oid = obj_ids[b];
    oid = min(max(oid, 0), NOBJ - 1);
    const float4* __restrict__ pb4 =
        reinterpret_cast<const float4*>(points + (size_t)oid * (NPTS * 3));

    const float4 a0 = pb4[3*lane + 0],    a1 = pb4[3*lane + 1],     a2v = pb4[3*lane + 2];
    const float4 b0 = pb4[3*(lane+32)],   b1 = pb4[3*(lane+32)+1],  b2v = pb4[3*(lane+32)+2];

    // ---- warp 0, lanes 0..7: coefficient chain for all 8 batch elements ----
    if (warp_in_blk == 0 && lane < WARPS_PB) {
        const int be = blockIdx.x * WARPS_PB + lane;
        const float4 qp = reinterpret_cast<const float4*>(pred_r)[be];
        const float4 qg = reinterpret_cast<const float4*>(gt_r)[be];
        const float pw = qp.x, px_ = qp.y, py_ = qp.z, pz_ = qp.w;
        const float gw = qg.x, gx_ = qg.y, gy_ = qg.z, gz_ = qg.w;

        const float m00 = -2.f*(py_*py_ + pz_*pz_ - gy_*gy_ - gz_*gz_);
        const float m01 =  2.f*(px_*py_ - pw*pz_ - gx_*gy_ + gw*gz_);
        const float m02 =  2.f*(px_*pz_ + pw*py_ - gx_*gz_ - gw*gy_);
        const float m10 =  2.f*(px_*py_ + pw*pz_ - gx_*gy_ - gw*gz_);
        const float m11 = -2.f*(px_*px_ + pz_*pz_ - gx_*gx_ - gz_*gz_);
        const float m12 =  2.f*(py_*pz_ - pw*px_ - gy_*gz_ + gw*gx_);
        const float m20 =  2.f*(px_*pz_ - pw*py_ - gx_*gz_ + gw*gy_);
        const float m21 =  2.f*(py_*pz_ + pw*px_ - gy_*gz_ - gw*gx_);
        const float m22 = -2.f*(px_*px_ + py_*py_ - gx_*gx_ - gy_*gy_);

        const float tx = pred_t[3*be+0] - gt_t[3*be+0];
        const float ty = pred_t[3*be+1] - gt_t[3*be+1];
        const float tz = pred_t[3*be+2] - gt_t[3*be+2];
        const float t2 = tx*tx + ty*ty + tz*tz;

        sh_coef[lane][0]  = m00*m00 + m10*m10 + m20*m20;        // s00
        sh_coef[lane][1]  = m01*m01 + m11*m11 + m21*m21;        // s11
        sh_coef[lane][2]  = m02*m02 + m12*m12 + m22*m22;        // s22
        sh_coef[lane][3]  = 2.f*(m00*m01 + m10*m11 + m20*m21);  // s01d
        sh_coef[lane][4]  = 2.f*(m00*m02 + m10*m12 + m20*m22);  // s02d
        sh_coef[lane][5]  = 2.f*(m01*m02 + m11*m12 + m21*m22);  // s12d
        sh_coef[lane][6]  = 2.f*(m00*tx + m10*ty + m20*tz);     // c0
        sh_coef[lane][7]  = 2.f*(m01*tx + m11*ty + m21*tz);     // c1
        sh_coef[lane][8]  = 2.f*(m02*tx + m12*ty + m22*tz);     // c2
        sh_coef[lane][9]  = t2;
    }
    __syncthreads();

    // broadcast LDS reads (sh_coef rows are 48B -> float4 aligned)
    const float4 k0 = *reinterpret_cast<const float4*>(&sh_coef[warp_in_blk][0]);
    const float4 k1 = *reinterpret_cast<const float4*>(&sh_coef[warp_in_blk][4]);
    const float4 k2 = *reinterpret_cast<const float4*>(&sh_coef[warp_in_blk][8]);
    const float s00 = k0.x, s11 = k0.y, s22 = k0.z, s01 = k0.w;
    const float s02 = k1.x, s12 = k1.y, c0  = k1.z, c1  = k1.w;
    const float c2  = k2.x, t2  = k2.y;

    float acc0 = 0.f, acc1 = 0.f;

    #define POINT_TERM(PX, PY, PZ, ACC) do {                                   \
        const float _px = (PX), _py = (PY), _pz = (PZ);                        \
        const float _U  = fmaf(s02, _pz, fmaf(s01, _py, s00*_px));             \
        const float _V  = fmaf(s12, _pz, s11*_py);                             \
        const float _W  = s22*_pz;                                             \
        const float _a2 = fmaf(_pz, _W, fmaf(_py, _V, _px*_U));                \
        const float _ln = fmaf(c0, _px, fmaf(c1, _py, fmaf(c2, _pz, t2)));     \
        const float _b2 = _a2 + _ln;                                           \
        ACC += sqrt_abs(_a2) + sqrt_abs(_b2);                                  \
    } while (0)

    #define QUAD(V0, V1, V2) do {                                              \
        POINT_TERM((V0).x, (V0).y, (V0).z, acc0);                              \
        POINT_TERM((V0).w, (V1).x, (V1).y, acc1);                              \
        POINT_TERM((V1).z, (V1).w, (V2).x, acc0);                              \
        POINT_TERM((V2).y, (V2).z, (V2).w, acc1);                              \
    } while (0)

    QUAD(a0, a1, a2v);

    const float4 d0 = pb4[3*(lane+64)], d1 = pb4[3*(lane+64)+1], d2v = pb4[3*(lane+64)+2];
    QUAD(b0, b1, b2v);

    if (lane < NQUADS - 96) {   // lane < 29: 4th strided quad
        const float4 e0 = pb4[3*(lane+96)], e1 = pb4[3*(lane+96)+1], e2v = pb4[3*(lane+96)+2];
        QUAD(d0, d1, d2v);
        QUAD(e0, e1, e2v);
    } else {
        QUAD(d0, d1, d2v);
    }
    #undef QUAD
    #undef POINT_TERM

    float s = acc0 + acc1;

    // warp reduce (fixed order -> deterministic)
    #pragma unroll
    for (int off = 16; off > 0; off >>= 1)
        s += __shfl_down_sync(0xffffffffu, s, off);

    if (lane == 0)
        sh_val[warp_in_blk] = fmaf(s, 1.0f / NPTS, sqrt_abs(t2));
    __syncthreads();

    if (threadIdx.x == 0) {
        float blk = 0.f;
        #pragma unroll
        for (int w = 0; w < WARPS_PB; w++) blk += sh_val[w];

        const u64 q = (u64)__double2ll_rn((double)blk * FP_SCALE);
        atomicAdd(&g_sum, q);
        __threadfence();
        const unsigned int ticket = atomicAdd(&g_count, 1u);
        if (ticket == NBLOCKS - 1) {
            const u64 total = atomicExch(&g_sum, 0ULL);  // read + reset for replay
            g_count = 0u;
            out[0] = (float)((double)total * INV_FP_SCALE * (1.0 / BATCH));
        }
    }
}

extern "C" void kernel_launch(void* const* d_in, const int* in_sizes, int n_in,
                              void* d_out, int out_size)
{
    const float* pred_r  = (const float*)d_in[0];
    const float* pred_t  = (const float*)d_in[1];
    const float* gt_r    = (const float*)d_in[2];
    const float* gt_t    = (const float*)d_in[3];
    const int*   obj_ids = (const int*)  d_in[4];
    const float* points  = (const float*)d_in[5];
    float* out = (float*)d_out;

    addloss_kernel<<<NBLOCKS, THREADS_PB>>>(pred_r, pred_t, gt_r, gt_t,
                                            obj_ids, points, out);
}

// round 11
// speedup vs baseline: 1.2262x; 1.1047x over previous
#include <cuda_runtime.h>

// ADDLoss — single launch; 8 lanes per batch element, 4 elements per warp.
//   out = mean_b( mean_n||Mp_n + t|| + mean_n||Mp_n|| + ||t|| ), M = Rp-Rg, t = tp-tg
// 4096 warps / 512 blocks: per-warp prologue+epilogue fixed cost amortized 4x
// vs warp-per-element, and the grid fits a SINGLE wave (no wave transitions).
// No barriers / extra launches (R7/R8/R10 lesson: all sync schemes cost more
// than inline redundancy). Per point: a2 = p^T S p (Horner), b2 = a2 + c.p + t2,
// sqrt.approx with folded |x|. Deterministic fixed-point integer reduce.

#define BATCH      16384
#define NPTS       500
#define NQUADS     125                  // 4 points per quad (3 x float4)
#define NOBJ       30
#define WARPS_PB   8
#define THREADS_PB (WARPS_PB * 32)      // 256
#define ELEMS_PW   4                    // elements per warp (8 lanes each)
#define NBLOCKS    (BATCH / (WARPS_PB * ELEMS_PW))   // 512

#define FP_SCALE     68719476736.0      // 2^36
#define INV_FP_SCALE (1.0 / 68719476736.0)

typedef unsigned long long u64;

__device__ u64 g_sum;                   // zero-init; self-resets each launch
__device__ unsigned int g_count;

__device__ __forceinline__ float sqrt_abs(float x) {
    float r; asm("sqrt.approx.f32 %0, %1;" : "=f"(r) : "f"(fabsf(x))); return r;
}

__global__ __launch_bounds__(THREADS_PB)
void addloss_kernel(const float* __restrict__ pred_r,
                    const float* __restrict__ pred_t,
                    const float* __restrict__ gt_r,
                    const float* __restrict__ gt_t,
                    const int*   __restrict__ obj_ids,
                    const float* __restrict__ points,
                    float*       __restrict__ out)
{
    const int warp_in_blk = threadIdx.x >> 5;
    const int lane        = threadIdx.x & 31;
    const int l8          = lane & 7;            // lane within element group
    const int quarter     = lane >> 3;           // which of 4 elements
    const int b = (blockIdx.x * WARPS_PB + warp_in_blk) * ELEMS_PW + quarter;

    __shared__ float sh_val[WARPS_PB];

    // ---- per-element prologue (replicated across the 8 lanes of a group) ----
    int oid = obj_ids[b];
    oid = min(max(oid, 0), NOBJ - 1);
    // object offset = oid*1500 floats = 6000 B (16B aligned) -> float4 legal
    const float4* __restrict__ pb4 =
        reinterpret_cast<const float4*>(points + (size_t)oid * (NPTS * 3));

    const float4 qp = reinterpret_cast<const float4*>(pred_r)[b];
    const float4 qg = reinterpret_cast<const float4*>(gt_r)[b];
    const float pw = qp.x, px_ = qp.y, py_ = qp.z, pz_ = qp.w;
    const float gw = qg.x, gx_ = qg.y, gy_ = qg.z, gz_ = qg.w;

    const float m00 = -2.f*(py_*py_ + pz_*pz_ - gy_*gy_ - gz_*gz_);
    const float m01 =  2.f*(px_*py_ - pw*pz_ - gx_*gy_ + gw*gz_);
    const float m02 =  2.f*(px_*pz_ + pw*py_ - gx_*gz_ - gw*gy_);
    const float m10 =  2.f*(px_*py_ + pw*pz_ - gx_*gy_ - gw*gz_);
    const float m11 = -2.f*(px_*px_ + pz_*pz_ - gx_*gx_ - gz_*gz_);
    const float m12 =  2.f*(py_*pz_ - pw*px_ - gy_*gz_ + gw*gx_);
    const float m20 =  2.f*(px_*pz_ - pw*py_ - gx_*gz_ + gw*gy_);
    const float m21 =  2.f*(py_*pz_ + pw*px_ - gy_*gz_ - gw*gx_);
    const float m22 = -2.f*(px_*px_ + py_*py_ - gx_*gx_ - gy_*gy_);

    const float tx = pred_t[3*b+0] - gt_t[3*b+0];
    const float ty = pred_t[3*b+1] - gt_t[3*b+1];
    const float tz = pred_t[3*b+2] - gt_t[3*b+2];
    const float t2 = tx*tx + ty*ty + tz*tz;

    const float s00 = m00*m00 + m10*m10 + m20*m20;
    const float s11 = m01*m01 + m11*m11 + m21*m21;
    const float s22 = m02*m02 + m12*m12 + m22*m22;
    const float s01 = 2.f*(m00*m01 + m10*m11 + m20*m21);
    const float s02 = 2.f*(m00*m02 + m10*m12 + m20*m22);
    const float s12 = 2.f*(m01*m02 + m11*m12 + m21*m22);
    const float c0  = 2.f*(m00*tx + m10*ty + m20*tz);
    const float c1  = 2.f*(m01*tx + m11*ty + m21*tz);
    const float c2  = 2.f*(m02*tx + m12*ty + m22*tz);

    float acc0 = 0.f, acc1 = 0.f;

    // 13 FFMA-class + 2 MUFU + 2 FADD per point
    #define POINT_TERM(PX, PY, PZ, ACC) do {                                   \
        const float _px = (PX), _py = (PY), _pz = (PZ);                        \
        const float _U  = fmaf(s02, _pz, fmaf(s01, _py, s00*_px));             \
        const float _V  = fmaf(s12, _pz, s11*_py);                             \
        const float _W  = s22*_pz;                                             \
        const float _a2 = fmaf(_pz, _W, fmaf(_py, _V, _px*_U));                \
        const float _ln = fmaf(c0, _px, fmaf(c1, _py, fmaf(c2, _pz, t2)));     \
        const float _b2 = _a2 + _ln;                                           \
        ACC += sqrt_abs(_a2) + sqrt_abs(_b2);                                  \
    } while (0)

    #define QUAD(Q) do {                                                       \
        const float4 _v0 = pb4[3*(Q) + 0];                                     \
        const float4 _v1 = pb4[3*(Q) + 1];                                     \
        const float4 _v2 = pb4[3*(Q) + 2];                                     \
        POINT_TERM(_v0.x, _v0.y, _v0.z, acc0);                                 \
        POINT_TERM(_v0.w, _v1.x, _v1.y, acc1);                                 \
        POINT_TERM(_v1.z, _v1.w, _v2.x, acc0);                                 \
        POINT_TERM(_v2.y, _v2.z, _v2.w, acc1);                                 \
    } while (0)

    // 125 quads over 8 lanes: 15 strided quads each + tail quad for l8 < 5.
    #pragma unroll
    for (int k = 0; k < 15; ++k)
        QUAD(l8 + 8*k);
    if (l8 < NQUADS - 120)   // l8 < 5 -> quads 120..124
        QUAD(120 + l8);

    #undef QUAD
    #undef POINT_TERM

    // ---- 8-lane segment reduce (fixed order -> deterministic) ----
    float s = acc0 + acc1;
    s += __shfl_down_sync(0xffffffffu, s, 4, 8);
    s += __shfl_down_sync(0xffffffffu, s, 2, 8);
    s += __shfl_down_sync(0xffffffffu, s, 1, 8);

    // element total (valid on l8==0 lanes): mean over points + trans norm
    const float s_elem = fmaf(s, 1.0f / NPTS, sqrt_abs(t2));

    // combine the 4 element totals of this warp on lane 0 (fixed order)
    const float e1 = __shfl_sync(0xffffffffu, s_elem, 8);
    const float e2 = __shfl_sync(0xffffffffu, s_elem, 16);
    const float e3 = __shfl_sync(0xffffffffu, s_elem, 24);

    if (lane == 0)
        sh_val[warp_in_blk] = ((s_elem + e1) + (e2 + e3));
    __syncthreads();

    if (threadIdx.x == 0) {
        float blk = 0.f;
        #pragma unroll
        for (int w = 0; w < WARPS_PB; w++) blk += sh_val[w];

        // deterministic grid reduction: fixed-point integer atomic
        const u64 q = (u64)__double2ll_rn((double)blk * FP_SCALE);
        atomicAdd(&g_sum, q);
        __threadfence();
        const unsigned int ticket = atomicAdd(&g_count, 1u);
        if (ticket == NBLOCKS - 1) {
            const u64 total = atomicExch(&g_sum, 0ULL);  // read + reset for replay
            g_count = 0u;
            out[0] = (float)((double)total * INV_FP_SCALE * (1.0 / BATCH));
        }
    }
}

extern "C" void kernel_launch(void* const* d_in, const int* in_sizes, int n_in,
                              void* d_out, int out_size)
{
    const float* pred_r  = (const float*)d_in[0];
    const float* pred_t  = (const float*)d_in[1];
    const float* gt_r    = (const float*)d_in[2];
    const float* gt_t    = (const float*)d_in[3];
    const int*   obj_ids = (const int*)  d_in[4];
    const float* points  = (const float*)d_in[5];
    float* out = (float*)d_out;

    addloss_kernel<<<NBLOCKS, THREADS_PB>>>(pred_r, pred_t, gt_r, gt_t,
                                            obj_ids, points, out);
}